// round 4
// baseline (speedup 1.0000x reference)
#include <cuda_runtime.h>
#include <cstdint>
#include <cstddef>

#define D    4096
#define NH   32
#define H    128
#define S    4096
#define KMASK (-2.3819763e+38f)

// ---------------- scratch (device globals; no allocation allowed) ----------
__device__ __align__(16) float g_qkvp[64 * 96 * 128];   // qkv gemv partials
__device__ __align__(16) float g_q[NH * H];             // rope'd + scaled q
__device__ __align__(16) float g_knew[NH * H];          // rope'd new k row
__device__ __align__(16) float g_vnew[NH * H];          // new v row
__device__ __align__(16) float g_logits[NH * S];
__device__ float g_pm[NH * 64];                         // per-block partial max
__device__ float g_pl[NH * 64];                         // per-block partial sum
__device__ __align__(16) float g_encpart[32 * NH * H];  // [chunk][nh]
__device__ __align__(16) float g_opart[64 * D];         // [nh-chunk][d]
__device__ int g_cnt[8];                                // per-d-tile tickets

// ---------------- K1: qkv = x @ w_qkv, partial over D ----------------------
// grid (96, 16): blockIdx.x = s*32+n, blockIdx.y = D-chunk of 256
__global__ void __launch_bounds__(128) k_qkv_partial(const float* __restrict__ x,
                                                     const float* __restrict__ w) {
    int sn = blockIdx.x;
    int dchunk = blockIdx.y;
    int tid = threadIdx.x;
    int hv = tid & 31;
    int ds = tid >> 5;

    __shared__ float xs[256];
    int dbase = dchunk * 256;
    for (int i = tid; i < 256; i += 128) xs[i] = x[dbase + i];
    __syncthreads();

    const float4* wv = (const float4*)(w + (size_t)sn * D * H + (size_t)dbase * H);
    float4 acc = make_float4(0.f, 0.f, 0.f, 0.f);
    int d0 = ds * 64;
#pragma unroll 8
    for (int d = d0; d < d0 + 64; ++d) {
        float xv = xs[d];
        float4 wq = wv[d * 32 + hv];
        acc.x += xv * wq.x; acc.y += xv * wq.y;
        acc.z += xv * wq.z; acc.w += xv * wq.w;
    }
    int p = dchunk * 4 + ds;                      // 0..63
    ((float4*)g_qkvp)[((size_t)p * 96 + sn) * 32 + hv] = acc;
}

// ---------------- K2: reduce partials, RoPE, scatter new rows --------------
__global__ void __launch_bounds__(128) k_qkv_rope(const int* __restrict__ segp,
                                                  const int* __restrict__ tsp,
                                                  float* __restrict__ k_out,
                                                  float* __restrict__ v_out) {
    int sn = blockIdx.x;
    int h = threadIdx.x;
    int s = sn >> 5, n = sn & 31;

    float val = 0.f;
#pragma unroll
    for (int p = 0; p < 64; ++p) val += g_qkvp[((size_t)p * 96 + sn) * 128 + h];

    __shared__ float sm[128];
    sm[h] = val;
    __syncthreads();

    int ts = tsp[0];
    if (s == 2) {
        g_vnew[n * 128 + h] = val;
        v_out[((size_t)ts * NH + n) * H + h] = val;
        return;
    }
    float pos = (float)segp[0];
    int i = h & 63;
    float timescale = powf(10000.f, (float)i * (1.f / 64.f));
    float ang = pos / timescale;
    float sn_, cs;
    sincosf(ang, &sn_, &cs);
    float out;
    if (h < 64) out = sm[h] * cs - sm[h + 64] * sn_;
    else        out = sm[h] * cs + sm[h - 64] * sn_;
    if (s == 0) {
        g_q[n * 128 + h] = out * 0.08838834764831845f;  // head_dim^-0.5
    } else {
        g_knew[n * 128 + h] = out;
        k_out[((size_t)ts * NH + n) * H + h] = out;
    }
}

// ---------------- K3: logits + k-cache copy + partial softmax stats --------
// grid (S/64, NH), block 256 = 8 warps; each warp does 8 (s,n) rows
__global__ void __launch_bounds__(256) k_logits_kcopy(const float* __restrict__ k_in,
                                                      const float* __restrict__ mask,
                                                      const int* __restrict__ tsp,
                                                      float* __restrict__ k_out) {
    int warp = threadIdx.x >> 5;
    int lane = threadIdx.x & 31;
    int n = blockIdx.y;
    int s0 = blockIdx.x * 64 + warp * 8;
    int ts = tsp[0];

    float4 qq = ((const float4*)g_q)[n * 32 + lane];

    // front-batched loads (MLP 8)
    float4 kk[8];
#pragma unroll
    for (int i = 0; i < 8; ++i) {
        int s = s0 + i;
        size_t ridx = (((size_t)s * NH + n) * H) >> 2;
        kk[i] = (s == ts) ? ((const float4*)g_knew)[n * 32 + lane]
                          : ((const float4*)k_in)[ridx + lane];
    }
#pragma unroll
    for (int i = 0; i < 8; ++i) {
        int s = s0 + i;
        if (s != ts) {
            size_t ridx = (((size_t)s * NH + n) * H) >> 2;
            ((float4*)k_out)[ridx + lane] = kk[i];
        }
    }

    float m = -3.4e38f, l = 0.f;
#pragma unroll
    for (int i = 0; i < 8; ++i) {
        int s = s0 + i;
        float dot = kk[i].x * qq.x + kk[i].y * qq.y + kk[i].z * qq.z + kk[i].w * qq.w;
#pragma unroll
        for (int off = 16; off; off >>= 1)
            dot += __shfl_xor_sync(0xffffffffu, dot, off);
        float lg = (mask[s] >= 0.5f * KMASK) ? dot : KMASK;
        if (lane == 0) g_logits[(size_t)n * S + s] = lg;
        float nm = fmaxf(m, lg);
        l = l * __expf(m - nm) + __expf(lg - nm);
        m = nm;
    }

    // block-level merge of 8 per-warp (m,l)
    __shared__ float sm_m[8], sm_l[8];
    if (lane == 0) { sm_m[warp] = m; sm_l[warp] = l; }
    __syncthreads();
    if (threadIdx.x == 0) {
        float bm = sm_m[0], bl = sm_l[0];
#pragma unroll
        for (int w = 1; w < 8; ++w) {
            float nm = fmaxf(bm, sm_m[w]);
            bl = bl * __expf(bm - nm) + sm_l[w] * __expf(sm_m[w] - nm);
            bm = nm;
        }
        g_pm[n * 64 + blockIdx.x] = bm;
        g_pl[n * 64 + blockIdx.x] = bl;
    }
}

// ---------------- K5: encoded partials + v-cache copy (stats fused) --------
// grid (32 s-chunks of 128, NH), block 256 = 8 warps; warp handles 16 s rows
__global__ void __launch_bounds__(256) k_enc_partial(const float* __restrict__ v_in,
                                                     const int* __restrict__ tsp,
                                                     float* __restrict__ v_out) {
    int c = blockIdx.x;
    int n = blockIdx.y;
    int warp = threadIdx.x >> 5;
    int lane = threadIdx.x & 31;
    int ts = tsp[0];

    // stats prologue: merge 64 (m,l) partials for this head (warp 0 only)
    __shared__ float s_mx, s_inv;
    if (threadIdx.x < 32) {
        float m = -3.4e38f, l = 0.f;
#pragma unroll
        for (int i = 0; i < 2; ++i) {
            float m2 = g_pm[n * 64 + lane + i * 32];
            float l2 = g_pl[n * 64 + lane + i * 32];
            float nm = fmaxf(m, m2);
            l = l * __expf(m - nm) + l2 * __expf(m2 - nm);
            m = nm;
        }
#pragma unroll
        for (int off = 16; off; off >>= 1) {
            float m2 = __shfl_xor_sync(0xffffffffu, m, off);
            float l2 = __shfl_xor_sync(0xffffffffu, l, off);
            float nm = fmaxf(m, m2);
            l = l * __expf(m - nm) + l2 * __expf(m2 - nm);
            m = nm;
        }
        if (lane == 0) { s_mx = m; s_inv = 1.f / l; }
    }
    __syncthreads();
    float mx = s_mx, inv = s_inv;
    const float* lg = g_logits + (size_t)n * S;

    float4 acc = make_float4(0.f, 0.f, 0.f, 0.f);
    int s0 = c * 128 + warp;
#pragma unroll 8
    for (int i = 0; i < 16; ++i) {
        int s = s0 + i * 8;
        size_t ridx = (((size_t)s * NH + n) * H) >> 2;
        float4 vv;
        if (s == ts) {
            vv = ((const float4*)g_vnew)[n * 32 + lane];
        } else {
            vv = ((const float4*)v_in)[ridx + lane];
            ((float4*)v_out)[ridx + lane] = vv;
        }
        float p = __expf(lg[s] - mx) * inv;
        acc.x += p * vv.x; acc.y += p * vv.y;
        acc.z += p * vv.z; acc.w += p * vv.w;
    }

    __shared__ float4 red[8][32];
    red[warp][lane] = acc;
    __syncthreads();
    if (warp == 0) {
        float4 t = red[0][lane];
#pragma unroll
        for (int w = 1; w < 8; ++w) {
            float4 o = red[w][lane];
            t.x += o.x; t.y += o.y; t.z += o.z; t.w += o.w;
        }
        ((float4*)g_encpart)[((size_t)c * NH + n) * 32 + lane] = t;
    }
}

// ---------------- K6: output GEMV partials + fused final reduce -------------
// grid (8 d-tiles of 512, 64 nh-chunks of 64), block 128: thread owns 4 d
__global__ void __launch_bounds__(128) k_out_gemv(const float* __restrict__ w_out,
                                                  float* __restrict__ attn) {
    __shared__ float enc_s[64];
    int tid = threadIdx.x;
    int nh0 = blockIdx.y * 64;
    if (tid < 64) {
        float v = 0.f;
#pragma unroll
        for (int c = 0; c < 32; ++c) v += g_encpart[(size_t)c * NH * H + nh0 + tid];
        enc_s[tid] = v;
    }
    __syncthreads();

    int d4 = blockIdx.x * 128 + tid;             // float4 index over d
    const float4* wv = (const float4*)w_out;
    float4 acc = make_float4(0.f, 0.f, 0.f, 0.f);
#pragma unroll 8
    for (int j = 0; j < 64; ++j) {
        float e = enc_s[j];
        float4 w4 = wv[(size_t)(nh0 + j) * (D / 4) + d4];
        acc.x += e * w4.x; acc.y += e * w4.y;
        acc.z += e * w4.z; acc.w += e * w4.w;
    }
    ((float4*)g_opart)[(size_t)blockIdx.y * (D / 4) + d4] = acc;

    // last block of this d-tile reduces all 64 nh-chunk partials
    __threadfence();
    __shared__ bool last;
    if (tid == 0)
        last = (atomicAdd(&g_cnt[blockIdx.x], 1) == 63);
    __syncthreads();
    if (last) {
        float4 v = make_float4(0.f, 0.f, 0.f, 0.f);
#pragma unroll
        for (int cc = 0; cc < 64; ++cc) {
            float4 o = ((const float4*)g_opart)[(size_t)cc * (D / 4) + d4];
            v.x += o.x; v.y += o.y; v.z += o.z; v.w += o.w;
        }
        ((float4*)attn)[d4] = v;
        if (tid == 0) g_cnt[blockIdx.x] = 0;    // reset for next replay
    }
}

// ---------------- launch ----------------------------------------------------
extern "C" void kernel_launch(void* const* d_in, const int* in_sizes, int n_in,
                              void* d_out, int out_size) {
    const float* x      = (const float*)d_in[0];
    const float* w_qkv  = (const float*)d_in[1];
    const float* w_out  = (const float*)d_in[2];
    const float* k_in   = (const float*)d_in[3];
    const float* v_in   = (const float*)d_in[4];
    const float* mask   = (const float*)d_in[5];
    const int*   segp   = (const int*)d_in[6];
    const int*   tsp    = (const int*)d_in[7];

    float* out   = (float*)d_out;
    float* k_out = out;
    float* v_out = out + (size_t)S * NH * H;
    float* attn  = out + 2ull * S * NH * H;

    k_qkv_partial<<<dim3(96, 16), 128>>>(x, w_qkv);
    k_qkv_rope<<<96, 128>>>(segp, tsp, k_out, v_out);
    k_logits_kcopy<<<dim3(S / 64, NH), 256>>>(k_in, mask, tsp, k_out);
    k_enc_partial<<<dim3(32, NH), 256>>>(v_in, tsp, v_out);
    k_out_gemv<<<dim3(8, 64), 128>>>(w_out, attn);
}